// round 2
// baseline (speedup 1.0000x reference)
#include <cuda_runtime.h>
#include <math.h>

// Problem constants (fixed shapes from reference)
#define NCLS 22
#define NB   2
#define HH   480
#define WW   640
#define SKIP 8
#define HS   (HH/SKIP)      // 60
#define WS   (WW/SKIP)      // 80
#define PP   (HS*WS)        // 4800
#define EPSF 1e-8f

// Vote kernel tiling
#define JPB    64           // target points per block (2 per lane)
#define NWARP  16           // i-loop split (warps per block)
#define VBLK   512
#define NJB    (PP/JPB)     // 75 j-blocks per batch
#define NFG    21           // foreground classes 1..21

// Scratch (allocation-free: __device__ globals)
__device__ float  g_us[NB*PP];     // prenormalized u (unsorted, deterministic)
__device__ float  g_vs[NB*PP];
__device__ float  g_zz[NB*PP];
__device__ int    g_lab[NB*PP];
__device__ int    g_cnt[NB*NCLS];  // per-class histogram (zeroed in finalize)
__device__ int    g_seg[NB*23];    // class segment starts (seg[22]=PP)
__device__ int    g_cur[NB*NCLS];  // scatter cursors
__device__ float4 g_pt[NB*PP];     // class-sorted (px,py,us,vs)
__device__ int    g_key[NB*NCLS];  // packed (votes<<13)|(8191-j)

// ---------------------------------------------------------------------------
// Kernel A: subsample + channel gather + prenormalize + class histogram.
// Also zeroes the argmax keys.
// ---------------------------------------------------------------------------
__global__ void hv_precompute(const int* __restrict__ lab2d,
                              const float* __restrict__ vp) {
    int t = blockIdx.x * blockDim.x + threadIdx.x;
    if (t < NB*NCLS) g_key[t] = 0;
    if (t >= NB*PP) return;
    int n = t / PP, p = t % PP;
    int r = p / WS, c = p % WS;
    int y = r * SKIP, x = c * SKIP;
    int lab = lab2d[(n*HH + y)*WW + x];
    const float* base = vp + (size_t)n * (3*NCLS) * HH * WW;
    size_t off = (size_t)(3*lab) * HH * WW + (size_t)y * WW + x;
    float u = base[off];
    float v = base[off + (size_t)HH*WW];
    float z = base[off + (size_t)2*HH*WW];
    float nrm = sqrtf(u*u + v*v) + EPSF;
    g_us[t] = u / nrm;
    g_vs[t] = v / nrm;
    g_zz[t] = z;
    g_lab[t] = lab;
    atomicAdd(&g_cnt[n*NCLS + lab], 1);
}

// ---------------------------------------------------------------------------
// Kernel B: tiny exclusive scan per batch -> segment starts + scatter cursors.
// ---------------------------------------------------------------------------
__global__ void hv_scan() {
    int n = threadIdx.x;
    if (n >= NB) return;
    int base = 0;
    for (int c = 0; c < NCLS; ++c) {
        g_seg[n*23 + c] = base;
        g_cur[n*NCLS + c] = base;
        base += g_cnt[n*NCLS + c];
    }
    g_seg[n*23 + 22] = base;   // == PP
}

// ---------------------------------------------------------------------------
// Kernel C: scatter points into class-sorted float4 array.
// (Order within a class is nondeterministic, but only integer vote counts are
// derived from it -> final output stays deterministic.)
// ---------------------------------------------------------------------------
__global__ void hv_scatter() {
    int t = blockIdx.x * blockDim.x + threadIdx.x;
    if (t >= NB*PP) return;
    int n = t / PP, p = t % PP;
    int lab = g_lab[t];
    int pos = atomicAdd(&g_cur[n*NCLS + lab], 1);
    float4 rec;
    rec.x = (float)((p % WS) * SKIP);
    rec.y = (float)((p / WS) * SKIP);
    rec.z = g_us[t];
    rec.w = g_vs[t];
    g_pt[n*PP + pos] = rec;
}

// ---------------------------------------------------------------------------
// Kernel 2: O(P^2) voting, no per-pair atomics.
// Block = 64 j's x 16 i-warps. For each class segment (labels uniform),
// each lane accumulates 2 register counters, stores once to SMEM vb.
// Then per-class block argmax -> global atomicMax on packed (votes, j) key.
// Packing: key = (votes << 13) | (8191 - j): higher votes win, ties -> min j
// (matching jnp.argmax first-max semantics).
// ---------------------------------------------------------------------------
__global__ void __launch_bounds__(VBLK) hv_vote() {
    __shared__ unsigned short vb[NFG * NWARP * JPB];   // 43 KB

    int n  = blockIdx.x / NJB;
    int jb = blockIdx.x % NJB;
    int tid = threadIdx.x;
    int jt = tid & 31;           // lane -> j pair (jt, jt+32)
    int is = tid >> 5;           // warp -> i slice

    int j0 = jb * JPB + jt;
    int j1 = j0 + 32;
    float px0 = (float)((j0 % WS) * SKIP), py0 = (float)((j0 / WS) * SKIP);
    float px1 = (float)((j1 % WS) * SKIP), py1 = (float)((j1 / WS) * SKIP);

    const float4* __restrict__ pt = g_pt + n*PP;
    const int* seg = g_seg + n*23;

    for (int ci = 0; ci < NFG; ++ci) {
        int c = ci + 1;
        int s = seg[c], e = seg[c+1];
        int cnt0 = 0, cnt1 = 0;
        int i = s + is;
        if (i < e) {
            float4 p = pt[i];
            while (true) {
                int inext = i + NWARP;
                bool more = inext < e;
                float4 pn;
                if (more) pn = pt[inext];    // prefetch (MLP=2)

                float dx0 = px0 - p.x, dy0 = py0 - p.y;
                float d20 = dx0*dx0 + dy0*dy0;
                float dot0 = p.z*dx0 + p.w*dy0;
                float dist0 = sqrtf(d20);
                if (d20 > 0.0f && dot0 >= 0.9f*(dist0 + EPSF)) ++cnt0;

                float dx1 = px1 - p.x, dy1 = py1 - p.y;
                float d21 = dx1*dx1 + dy1*dy1;
                float dot1 = p.z*dx1 + p.w*dy1;
                float dist1 = sqrtf(d21);
                if (d21 > 0.0f && dot1 >= 0.9f*(dist1 + EPSF)) ++cnt1;

                if (!more) break;
                p = pn; i = inext;
            }
        }
        vb[(ci*NWARP + is)*JPB + jt]      = (unsigned short)cnt0;
        vb[(ci*NWARP + is)*JPB + jt + 32] = (unsigned short)cnt1;
    }
    __syncthreads();

    // Reduce over the 16 i-warps; per-class key argmax.
    // tasks: 21 classes x 64 j = 1344; each 32-lane group has uniform class.
    for (int t = tid; t < NFG*JPB; t += VBLK) {
        int ci = t / JPB;          // warp-uniform (JPB=64, VBLK multiple of 64)
        int q  = t % JPB;
        int sum = 0;
        #pragma unroll
        for (int w = 0; w < NWARP; ++w)
            sum += vb[(ci*NWARP + w)*JPB + q];
        int jj = jb*JPB + q;
        unsigned key = ((unsigned)sum << 13) | (unsigned)(8191 - jj);
        unsigned wmax = __reduce_max_sync(0xFFFFFFFFu, key);
        if ((tid & 31) == 0)
            atomicMax((unsigned*)&g_key[n*NCLS + (ci+1)], wmax);
    }
}

// ---------------------------------------------------------------------------
// Kernel 3: one block per (n, c). Decode best/max_votes, recompute inliers
// toward best center over the UNSORTED arrays (deterministic float sum),
// emit top_box and top_pose rows. Also re-zeroes histogram for graph replay.
// ---------------------------------------------------------------------------
__global__ void hv_finalize(const float* __restrict__ extents,
                            const float* __restrict__ meta,
                            float* __restrict__ out) {
    __shared__ int   s_nin[256];
    __shared__ float s_zs[256];

    int n = blockIdx.x / NCLS;
    int c = blockIdx.x % NCLS;
    int tid = threadIdx.x;

    int key  = g_key[n*NCLS + c];
    int best = 8191 - (key & 8191);
    float mv = (float)(key >> 13);
    float pxb = (float)((best % WS) * SKIP);
    float pyb = (float)((best / WS) * SKIP);

    const float* us = g_us + n*PP;
    const float* vs = g_vs + n*PP;
    const float* zz = g_zz + n*PP;
    const int*   lb = g_lab + n*PP;

    int nin = 0;
    float zs = 0.0f;
    for (int i = tid; i < PP; i += 256) {
        int labi = lb[i];
        if (labi != c || labi == 0) continue;
        float dx = pxb - (float)((i % WS) * SKIP);
        float dy = pyb - (float)((i / WS) * SKIP);
        float d2 = dx*dx + dy*dy;
        float dist = sqrtf(d2);
        float dot  = us[i]*dx + vs[i]*dy;
        if (d2 > 0.0f && dot >= 0.9f*(dist + EPSF)) { ++nin; zs += zz[i]; }
    }
    s_nin[tid] = nin; s_zs[tid] = zs;
    __syncthreads();
    for (int s = 128; s > 0; s >>= 1) {
        if (tid < s) {
            s_nin[tid] += s_nin[tid+s];
            s_zs[tid]  += s_zs[tid+s];
        }
        __syncthreads();
    }

    if (tid == 0) {
        float count = (float)g_cnt[n*NCLS + c];
        bool valid = (count * (float)(SKIP*SKIP) >= 500.0f) &&
                     (mv >= 10.0f) &&
                     (mv >= 0.02f * count) &&
                     (c > 0);
        float vmf = valid ? 1.0f : 0.0f;
        float zm = s_zs[0] / fmaxf((float)s_nin[0], 1.0f);
        float zc = fmaxf(zm, 0.001f);
        float fx  = meta[n*9 + 0];
        float ppx = meta[n*9 + 2];
        float fy  = meta[n*9 + 4];
        float ppy = meta[n*9 + 5];
        float bw = extents[c*3 + 0] * fx / zc;
        float bh = extents[c*3 + 1] * fy / zc;
        float cx = pxb, cy = pyb;

        float* tb = out + (n*NCLS + c)*7;
        tb[0] = (float)n * vmf;
        tb[1] = (float)c * vmf;
        tb[2] = (cx - bw*0.5f) * vmf;
        tb[3] = (cy - bh*0.5f) * vmf;
        tb[4] = (cx + bw*0.5f) * vmf;
        tb[5] = (cy + bh*0.5f) * vmf;
        tb[6] = mv * vmf;

        float tx = (cx - ppx) * zc / fx;
        float ty = (cy - ppy) * zc / fy;
        float* tp = out + NB*NCLS*7 + (n*NCLS + c)*7;
        tp[0] = vmf;
        tp[1] = 0.0f;
        tp[2] = 0.0f;
        tp[3] = 0.0f;
        tp[4] = tx * vmf;
        tp[5] = ty * vmf;
        tp[6] = zc * vmf;

        g_cnt[n*NCLS + c] = 0;   // reset histogram for next graph replay
    }
}

extern "C" void kernel_launch(void* const* d_in, const int* in_sizes, int n_in,
                              void* d_out, int out_size) {
    const int*   lab2d   = (const int*)d_in[0];
    const float* vp      = (const float*)d_in[1];
    const float* extents = (const float*)d_in[2];
    // d_in[3] = poses (unused by reference output)
    const float* meta    = (const float*)d_in[4];
    float* out = (float*)d_out;

    hv_precompute<<<75, 128>>>(lab2d, vp);
    hv_scan<<<1, 32>>>();
    hv_scatter<<<75, 128>>>();
    hv_vote<<<NB*NJB, VBLK>>>();
    hv_finalize<<<NB*NCLS, 256>>>(extents, meta, out);
}

// round 3
// speedup vs baseline: 1.7252x; 1.7252x over previous
#include <cuda_runtime.h>
#include <math.h>

// Problem constants (fixed shapes from reference)
#define NCLS 22
#define NB   2
#define HH   480
#define WW   640
#define SKIP 8
#define HS   (HH/SKIP)      // 60
#define WS   (WW/SKIP)      // 80
#define PP   (HS*WS)        // 4800
#define EPSF 1e-8f

// Vote kernel tiling
#define JPB    32           // target points per block (1 per lane)
#define NWARP  32           // i-loop split (warps per block)
#define VBLK   1024
#define NJB    (PP/JPB)     // 150 j-blocks per batch
#define NFG    21           // foreground classes 1..21

// Scratch (allocation-free: __device__ globals)
__device__ float  g_us[NB*PP];     // prenormalized u (unsorted, deterministic)
__device__ float  g_vs[NB*PP];
__device__ float  g_zz[NB*PP];
__device__ int    g_lab[NB*PP];
__device__ int    g_cnt[NB*NCLS];  // per-class histogram (zeroed in finalize)
__device__ int    g_seg[NB*23];    // class segment starts (seg[22]=PP)
__device__ int    g_cur[NB*NCLS];  // scatter cursors
__device__ float4 g_pt[NB*PP];     // class-sorted (px,py,us,vs)
__device__ int    g_key[NB*NCLS];  // packed (votes<<13)|(8191-j)
__device__ float  g_lut[HS*WS];    // thr = 0.9*(dist+EPS) by (|dy|/8, |dx|/8)

// ---------------------------------------------------------------------------
// Kernel 0: distance-threshold LUT over the integer offset grid.
// lut[ady*80 + adx] = 0.9f*(sqrtf((8adx)^2+(8ady)^2) + EPSF); center = +INF
// (encodes the dist>0 exclusion). Identical float ops to the reference chain.
// ---------------------------------------------------------------------------
__global__ void hv_lut() {
    int t = blockIdx.x * blockDim.x + threadIdx.x;
    if (t >= HS*WS) return;
    int ady = t / WS, adx = t % WS;
    float dx = (float)(adx * SKIP);
    float dy = (float)(ady * SKIP);
    float d2 = dx*dx + dy*dy;
    float dist = sqrtf(d2);
    float thr = 0.9f * (dist + EPSF);
    g_lut[t] = (t == 0) ? __int_as_float(0x7f800000) : thr;  // +INF at center
}

// ---------------------------------------------------------------------------
// Kernel A: subsample + channel gather + prenormalize + class histogram.
// Also zeroes the argmax keys.
// ---------------------------------------------------------------------------
__global__ void hv_precompute(const int* __restrict__ lab2d,
                              const float* __restrict__ vp) {
    int t = blockIdx.x * blockDim.x + threadIdx.x;
    if (t < NB*NCLS) g_key[t] = 0;
    if (t >= NB*PP) return;
    int n = t / PP, p = t % PP;
    int r = p / WS, c = p % WS;
    int y = r * SKIP, x = c * SKIP;
    int lab = lab2d[(n*HH + y)*WW + x];
    const float* base = vp + (size_t)n * (3*NCLS) * HH * WW;
    size_t off = (size_t)(3*lab) * HH * WW + (size_t)y * WW + x;
    float u = base[off];
    float v = base[off + (size_t)HH*WW];
    float z = base[off + (size_t)2*HH*WW];
    float nrm = sqrtf(u*u + v*v) + EPSF;
    g_us[t] = u / nrm;
    g_vs[t] = v / nrm;
    g_zz[t] = z;
    g_lab[t] = lab;
    atomicAdd(&g_cnt[n*NCLS + lab], 1);
}

// ---------------------------------------------------------------------------
// Kernel B: tiny exclusive scan per batch -> segment starts + scatter cursors.
// ---------------------------------------------------------------------------
__global__ void hv_scan() {
    int n = threadIdx.x;
    if (n >= NB) return;
    int base = 0;
    for (int c = 0; c < NCLS; ++c) {
        g_seg[n*23 + c] = base;
        g_cur[n*NCLS + c] = base;
        base += g_cnt[n*NCLS + c];
    }
    g_seg[n*23 + 22] = base;   // == PP
}

// ---------------------------------------------------------------------------
// Kernel C: scatter points into class-sorted float4 array.
// (Order within a class is nondeterministic, but only integer vote counts are
// derived from it -> final output stays deterministic.)
// ---------------------------------------------------------------------------
__global__ void hv_scatter() {
    int t = blockIdx.x * blockDim.x + threadIdx.x;
    if (t >= NB*PP) return;
    int n = t / PP, p = t % PP;
    int lab = g_lab[t];
    int pos = atomicAdd(&g_cur[n*NCLS + lab], 1);
    float4 rec;
    rec.x = (float)((p % WS) * SKIP);
    rec.y = (float)((p / WS) * SKIP);
    rec.z = g_us[t];
    rec.w = g_vs[t];
    g_pt[n*PP + pos] = rec;
}

// ---------------------------------------------------------------------------
// Kernel 2: O(P^2) voting. No atomics, no sqrt (shared-memory LUT).
// Block = 32 j's (one per lane) x 32 i-warps, 1024 threads, 2 blocks/SM
// -> 100% occupancy in one wave (300 blocks).
// Per class segment (label uniform): register counter per lane, u8 store.
// One barrier, then per-class cross-warp sum + key argmax -> global atomicMax.
// Packing: key = (votes << 13) | (8191 - j): higher votes win, ties -> min j
// (matching jnp.argmax first-max semantics).
// ---------------------------------------------------------------------------
__global__ void __launch_bounds__(VBLK, 2) hv_vote() {
    __shared__ float         slut[HS*WS];               // 18.75 KB
    __shared__ unsigned char vb[NFG * NWARP * JPB];     // 21 KB

    int n  = blockIdx.x / NJB;
    int jb = blockIdx.x % NJB;
    int tid = threadIdx.x;
    int jt = tid & 31;           // lane -> j
    int is = tid >> 5;           // warp -> i slice

    // Load LUT to shared
    for (int k = tid; k < HS*WS; k += VBLK) slut[k] = g_lut[k];
    __syncthreads();

    int j = jb * JPB + jt;
    float pxj = (float)((j % WS) * SKIP);
    float pyj = (float)((j / WS) * SKIP);

    const float4* __restrict__ pt = g_pt + n*PP;
    const int* seg = g_seg + n*23;

    for (int ci = 0; ci < NFG; ++ci) {
        int c = ci + 1;
        int s = seg[c], e = seg[c+1];
        int cnt = 0;
        #pragma unroll 2
        for (int i = s + is; i < e; i += NWARP) {
            float4 p = pt[i];                     // warp-uniform broadcast
            float dx = pxj - p.x;
            float dy = pyj - p.y;
            float dot = p.z*dx + p.w*dy;
            // idx = (|dy|/8)*80 + |dx|/8, exact integer-valued float math
            float fidx = fmaf(fabsf(dy), 10.0f, fabsf(dx)*0.125f);
            float thr = slut[(int)fidx];
            if (dot >= thr) ++cnt;
        }
        vb[(ci*NWARP + is)*JPB + jt] = (unsigned char)cnt;  // <= 150, fits u8
    }
    __syncthreads();

    // Per-class reduce over 32 i-warps + block argmax key -> global atomicMax.
    if (tid < NFG*32) {          // 21 full warps, ci warp-uniform
        int ci = tid >> 5;
        int q  = tid & 31;
        int sum = 0;
        #pragma unroll
        for (int w = 0; w < NWARP; ++w)
            sum += vb[(ci*NWARP + w)*JPB + q];
        int jj = jb*JPB + q;
        unsigned key = ((unsigned)sum << 13) | (unsigned)(8191 - jj);
        unsigned wmax = __reduce_max_sync(0xFFFFFFFFu, key);
        if (q == 0)
            atomicMax((unsigned*)&g_key[n*NCLS + (ci+1)], wmax);
    }
}

// ---------------------------------------------------------------------------
// Kernel 3: one block per (n, c). Decode best/max_votes, recompute inliers
// toward best center over the UNSORTED arrays (deterministic float sum),
// emit top_box and top_pose rows. Also re-zeroes histogram for graph replay.
// ---------------------------------------------------------------------------
__global__ void hv_finalize(const float* __restrict__ extents,
                            const float* __restrict__ meta,
                            float* __restrict__ out) {
    __shared__ int   s_nin[256];
    __shared__ float s_zs[256];

    int n = blockIdx.x / NCLS;
    int c = blockIdx.x % NCLS;
    int tid = threadIdx.x;

    int key  = g_key[n*NCLS + c];
    int best = 8191 - (key & 8191);
    float mv = (float)(key >> 13);
    float pxb = (float)((best % WS) * SKIP);
    float pyb = (float)((best / WS) * SKIP);

    const float* us = g_us + n*PP;
    const float* vs = g_vs + n*PP;
    const float* zz = g_zz + n*PP;
    const int*   lb = g_lab + n*PP;

    int nin = 0;
    float zs = 0.0f;
    for (int i = tid; i < PP; i += 256) {
        int labi = lb[i];
        if (labi != c || labi == 0) continue;
        float dx = pxb - (float)((i % WS) * SKIP);
        float dy = pyb - (float)((i / WS) * SKIP);
        float d2 = dx*dx + dy*dy;
        float dist = sqrtf(d2);
        float dot  = us[i]*dx + vs[i]*dy;
        if (d2 > 0.0f && dot >= 0.9f*(dist + EPSF)) { ++nin; zs += zz[i]; }
    }
    s_nin[tid] = nin; s_zs[tid] = zs;
    __syncthreads();
    for (int s = 128; s > 0; s >>= 1) {
        if (tid < s) {
            s_nin[tid] += s_nin[tid+s];
            s_zs[tid]  += s_zs[tid+s];
        }
        __syncthreads();
    }

    if (tid == 0) {
        float count = (float)g_cnt[n*NCLS + c];
        bool valid = (count * (float)(SKIP*SKIP) >= 500.0f) &&
                     (mv >= 10.0f) &&
                     (mv >= 0.02f * count) &&
                     (c > 0);
        float vmf = valid ? 1.0f : 0.0f;
        float zm = s_zs[0] / fmaxf((float)s_nin[0], 1.0f);
        float zc = fmaxf(zm, 0.001f);
        float fx  = meta[n*9 + 0];
        float ppx = meta[n*9 + 2];
        float fy  = meta[n*9 + 4];
        float ppy = meta[n*9 + 5];
        float bw = extents[c*3 + 0] * fx / zc;
        float bh = extents[c*3 + 1] * fy / zc;
        float cx = pxb, cy = pyb;

        float* tb = out + (n*NCLS + c)*7;
        tb[0] = (float)n * vmf;
        tb[1] = (float)c * vmf;
        tb[2] = (cx - bw*0.5f) * vmf;
        tb[3] = (cy - bh*0.5f) * vmf;
        tb[4] = (cx + bw*0.5f) * vmf;
        tb[5] = (cy + bh*0.5f) * vmf;
        tb[6] = mv * vmf;

        float tx = (cx - ppx) * zc / fx;
        float ty = (cy - ppy) * zc / fy;
        float* tp = out + NB*NCLS*7 + (n*NCLS + c)*7;
        tp[0] = vmf;
        tp[1] = 0.0f;
        tp[2] = 0.0f;
        tp[3] = 0.0f;
        tp[4] = tx * vmf;
        tp[5] = ty * vmf;
        tp[6] = zc * vmf;

        g_cnt[n*NCLS + c] = 0;   // reset histogram for next graph replay
    }
}

extern "C" void kernel_launch(void* const* d_in, const int* in_sizes, int n_in,
                              void* d_out, int out_size) {
    const int*   lab2d   = (const int*)d_in[0];
    const float* vp      = (const float*)d_in[1];
    const float* extents = (const float*)d_in[2];
    // d_in[3] = poses (unused by reference output)
    const float* meta    = (const float*)d_in[4];
    float* out = (float*)d_out;

    hv_lut<<<(HS*WS + 255)/256, 256>>>();
    hv_precompute<<<75, 128>>>(lab2d, vp);
    hv_scan<<<1, 32>>>();
    hv_scatter<<<75, 128>>>();
    hv_vote<<<NB*NJB, VBLK>>>();
    hv_finalize<<<NB*NCLS, 256>>>(extents, meta, out);
}